// round 17
// baseline (speedup 1.0000x reference)
#include <cuda_runtime.h>
#include <cuda_fp16.h>
#include <cstdint>

#define B_    32
#define D_    256
#define HW_   4096
#define K_    1024
#define NROWS (B_ * HW_)
#define TENSOR_ELEMS (B_ * D_ * HW_)
#define THRESH 1.5e-4f
#define SAFE   8.0e-5f

__device__ __half g_eh[K_ * D_];     // fp16 of (-2*E), k-major rows
__device__ float g_enorm[K_];
__device__ int   g_idx[NROWS];
__device__ float g_bsum[1024];
__device__ int   g_nlight, g_nheavy;
__device__ int   g_lrow[NROWS];
__device__ int   g_lcand[NROWS];     // i1 | (i2 << 16)
__device__ int   g_hrow[NROWS];

// ---------------- PTX helpers (plain sm_80-level, no 'a' features) ----------
__device__ __forceinline__ uint32_t smem_u32(const void* p) {
    uint32_t a;
    asm("{ .reg .u64 t; cvta.to.shared.u64 t, %1; cvt.u32.u64 %0, t; }" : "=r"(a) : "l"(p));
    return a;
}
__device__ __forceinline__ void cp16(uint32_t dst, const void* src) {
    asm volatile("cp.async.cg.shared.global [%0], [%1], 16;" :: "r"(dst), "l"(src) : "memory");
}
#define CP_COMMIT() asm volatile("cp.async.commit_group;" ::: "memory")
#define CP_WAIT0()  asm volatile("cp.async.wait_group 0;" ::: "memory")

__device__ __forceinline__ void ldsm4(uint32_t* r, uint32_t addr) {
    asm volatile("ldmatrix.sync.aligned.m8n8.x4.shared.b16 {%0,%1,%2,%3}, [%4];"
                 : "=r"(r[0]), "=r"(r[1]), "=r"(r[2]), "=r"(r[3]) : "r"(addr));
}
__device__ __forceinline__ void mma16816(float* c, const uint32_t* a, const uint32_t* b) {
    asm volatile("mma.sync.aligned.m16n8k16.row.col.f32.f16.f16.f32 "
                 "{%0,%1,%2,%3}, {%4,%5,%6,%7}, {%8,%9}, {%0,%1,%2,%3};"
                 : "+f"(c[0]), "+f"(c[1]), "+f"(c[2]), "+f"(c[3])
                 : "r"(a[0]), "r"(a[1]), "r"(a[2]), "r"(a[3]), "r"(b[0]), "r"(b[1]));
}

// merge sorted triple (w1,j1,w2,j2,w3) into (v1,i1,v2,i2,v3); lowest-index ties
__device__ __forceinline__ void merge5(float& v1, int& i1, float& v2, int& i2, float& v3,
                                       float w1, int j1, float w2, int j2, float w3) {
    if (w1 < v1 || (w1 == v1 && j1 < i1)) {
        float tv1 = v1; int ti1 = i1; float tv2 = v2;
        v1 = w1; i1 = j1;
        if (tv1 < w2 || (tv1 == w2 && ti1 < j2)) {
            v2 = tv1; i2 = ti1;
            v3 = fminf(tv2, w2);
        } else {
            float keep3 = w3;
            v2 = w2; i2 = j2;
            v3 = fminf(tv1, keep3);
        }
    } else {
        if (w1 < v2 || (w1 == v2 && j1 < i2)) {
            v3 = fminf(v2, w2);
            v2 = w1; i2 = j1;
        } else {
            v3 = fminf(v3, w1);
        }
    }
}

// smem layout (bytes): X 32K | B 2x32K | Se 4K | red 5.5K  -> 105 KB, occ 2
#define SM_XHI   0
#define SM_E     32768
#define SM_SE    98304
#define SM_RED   102400              // 64 pixels x 4 wn x 5 fields = 5120 B
#define SM_TOTAL 107520

// ---------------- dummy: keeps argmin in ncu's capture window ---------------
__global__ void dummy_kernel() {
    if (blockIdx.x > 1000) g_bsum[0] = 0.f;   // never true (grid = 1)
}

// ---------------- prep: fp16 of (-2E), ||e||^2 ------------------------------
__global__ void prep_kernel(const float* __restrict__ emb) {
    int k = blockIdx.x, d = threadIdx.x;
    g_eh[k * D_ + d] = __float2half(-2.0f * emb[k * D_ + d]);
    if (d == 0) {
        const float* r = emb + (size_t)k * D_;
        float s = 0.f;
        for (int i = 0; i < D_; ++i) { float v = r[i]; s = fmaf(v, v, s); }
        g_enorm[k] = s;
        if (k == 0) { g_nlight = 0; g_nheavy = 0; }
    }
}

// stage one 256-code x 64-d fp16 tile into a 32KB buffer (8 cp16/thread)
__device__ __forceinline__ void stage_B256(uint32_t ebase, const __half* Eptr, int tid) {
    #pragma unroll
    for (int i = 0; i < 8; ++i) {
        int idx = tid + i * 256;
        int r = idx >> 3, s = idx & 7;
        uint32_t dst = (uint32_t)((r >> 3) * 1024 + (r & 7) * 128 +
                                  ((s * 16) ^ ((r & 7) << 4)));
        cp16(ebase + dst, Eptr + (size_t)r * D_ + s * 8);
    }
    CP_COMMIT();
}

// ---------------- HMMA argmin: 64 pixels/CTA, warp tile 32x64, occ 2 --------
__global__ __launch_bounds__(256, 2)
void argmin_kernel(const float* __restrict__ x) {
    extern __shared__ char smem[];
    const uint32_t sb = smem_u32(smem);
    float* sSe  = (float*)(smem + SM_SE);
    float* red  = (float*)(smem + SM_RED);

    const int tid  = threadIdx.x;
    const int lane = tid & 31;
    const int w    = tid >> 5;
    const int wm   = w & 1;
    const int wn   = w >> 1;
    const int b    = blockIdx.x >> 6;
    const int c0   = (blockIdx.x & 63) * 64;

    for (int i = tid; i < K_; i += 256) sSe[i] = g_enorm[i];

    stage_B256(sb + SM_E, g_eh, tid);

    // stage X tile [64 pixels x 256 d] fp16, SW128 K-major
    {
        const int p = tid & 63, half = tid >> 6;
        const float* xb = x + (size_t)b * (D_ * HW_) + c0 + p;
        const uint32_t rowbase = (uint32_t)((p >> 3) * 1024 + (p & 7) * 128);
        const uint32_t rx = (uint32_t)((p & 7) << 4);
        for (int d0 = half * 64; d0 < half * 64 + 64; d0 += 8) {
            float v[8];
            #pragma unroll
            for (int i = 0; i < 8; ++i) v[i] = xb[(size_t)(d0 + i) * HW_];
            uint32_t hp[4];
            #pragma unroll
            for (int i = 0; i < 4; ++i) {
                __half h0 = __float2half(v[2*i]);
                __half h1 = __float2half(v[2*i+1]);
                hp[i] = (uint32_t)__half_as_ushort(h0) |
                        ((uint32_t)__half_as_ushort(h1) << 16);
            }
            uint32_t off = (uint32_t)(d0 >> 6) * 8192u + rowbase +
                           (((uint32_t)(d0 & 63) * 2u) ^ rx);
            *(uint4*)(smem + SM_XHI + off) = make_uint4(hp[0], hp[1], hp[2], hp[3]);
        }
    }

    uint32_t aOff[2], aXor[2];
    #pragma unroll
    for (int mt = 0; mt < 2; ++mt) {
        int r = wm * 32 + mt * 16 + (lane & 7) + ((lane >> 3) & 1) * 8;
        aOff[mt] = (uint32_t)((r >> 3) * 1024 + (r & 7) * 128);
        aXor[mt] = (uint32_t)((r & 7) << 4);
    }
    const uint32_t adB = (lane >> 4) ? 16u : 0u;
    uint32_t bpOff[4], bpXor[4];
    #pragma unroll
    for (int p = 0; p < 4; ++p) {
        int n = wn * 64 + p * 16 + ((lane >> 4) << 3) + (lane & 7);
        bpOff[p] = (uint32_t)((n >> 3) * 1024 + (n & 7) * 128);
        bpXor[p] = (uint32_t)((n & 7) << 4);
    }
    const uint32_t kB = (uint32_t)(((lane >> 3) & 1) << 4);

    // top-3 tracking per pixel slot: (m1,i1,m2,i2,m3)
    float m1r[4], m2r[4], m3r[4]; int i1r[4], i2r[4];
    #pragma unroll
    for (int s = 0; s < 4; ++s) {
        m1r[s] = 3.4e38f; m2r[s] = 3.4e38f; m3r[s] = 3.4e38f;
        i1r[s] = 0; i2r[s] = 0;
    }

    float acc[2][8][4];

    for (int seg = 0; seg < 16; ++seg) {
        const int ch = seg & 3;
        CP_WAIT0();
        __syncthreads();
        if (seg < 15) {
            const int ns = seg + 1;
            stage_B256(sb + SM_E + (uint32_t)(ns & 1) * 32768u,
                       g_eh + (size_t)(ns >> 2) * 256 * D_ + (ns & 3) * 64, tid);
        }

        if (ch == 0) {
            #pragma unroll
            for (int mt = 0; mt < 2; ++mt)
                #pragma unroll
                for (int nt = 0; nt < 8; ++nt)
                    #pragma unroll
                    for (int q = 0; q < 4; ++q) acc[mt][nt][q] = 0.f;
        }

        const uint32_t eh  = sb + SM_E + (uint32_t)(seg & 1) * 32768u;
        const uint32_t xco = (uint32_t)ch * 8192u;

        #pragma unroll
        for (int ks = 0; ks < 4; ++ks) {
            const uint32_t ksl = (uint32_t)ks * 32u;
            const uint32_t dA  = ksl + adB;
            uint32_t bh[8][2], ah[2][4];
            #pragma unroll
            for (int p = 0; p < 4; ++p) {
                uint32_t r4[4];
                ldsm4(r4, eh + bpOff[p] + ((ksl + kB) ^ bpXor[p]));
                bh[2*p][0] = r4[0]; bh[2*p][1] = r4[1];
                bh[2*p+1][0] = r4[2]; bh[2*p+1][1] = r4[3];
            }
            #pragma unroll
            for (int mt = 0; mt < 2; ++mt)
                ldsm4(ah[mt], sb + SM_XHI + xco + aOff[mt] + (dA ^ aXor[mt]));
            #pragma unroll
            for (int mt = 0; mt < 2; ++mt)
                #pragma unroll
                for (int nt = 0; nt < 8; ++nt)
                    mma16816(acc[mt][nt], ah[mt], bh[nt]);
        }

        if (ch == 3) {
            const int pass = seg >> 2;
            const int cbase = pass * 256 + wn * 64 + 2 * (lane & 3);
            #pragma unroll
            for (int nt = 0; nt < 8; ++nt) {
                const int code0 = cbase + nt * 8;
                const float se0 = sSe[code0], se1 = sSe[code0 + 1];
                #pragma unroll
                for (int mt = 0; mt < 2; ++mt) {
                    #pragma unroll
                    for (int q = 0; q < 4; ++q) {
                        const int s = mt * 2 + (q >> 1);
                        const int code = code0 + (q & 1);
                        const float se = (q & 1) ? se1 : se0;
                        float v = se + acc[mt][nt][q];
                        if (v < m1r[s]) {
                            m3r[s] = m2r[s]; m2r[s] = m1r[s]; i2r[s] = i1r[s];
                            m1r[s] = v; i1r[s] = code;
                        } else if (v < m2r[s]) {
                            m3r[s] = m2r[s]; m2r[s] = v; i2r[s] = code;
                        } else if (v < m3r[s]) {
                            m3r[s] = v;
                        }
                    }
                }
            }
        }
    }

    __syncthreads();
    // quad-lane reduce (same rows, different code groups), then smem across wn
    #pragma unroll
    for (int s = 0; s < 4; ++s) {
        float v1 = m1r[s], v2 = m2r[s], v3 = m3r[s];
        int   i1 = i1r[s], i2 = i2r[s];
        #pragma unroll
        for (int ofs = 1; ofs <= 2; ofs <<= 1) {
            float w1 = __shfl_xor_sync(0xffffffffu, v1, ofs);
            int   j1 = __shfl_xor_sync(0xffffffffu, i1, ofs);
            float w2 = __shfl_xor_sync(0xffffffffu, v2, ofs);
            int   j2 = __shfl_xor_sync(0xffffffffu, i2, ofs);
            float w3 = __shfl_xor_sync(0xffffffffu, v3, ofs);
            merge5(v1, i1, v2, i2, v3, w1, j1, w2, j2, w3);
        }
        if ((lane & 3) == 0) {
            int pix = wm * 32 + (s >> 1) * 16 + (lane >> 2) + (s & 1) * 8;
            float* rp = red + (pix * 4 + wn) * 5;
            rp[0] = v1; rp[1] = __int_as_float(i1);
            rp[2] = v2; rp[3] = __int_as_float(i2);
            rp[4] = v3;
        }
    }
    __syncthreads();

    if (tid < 64) {
        const float* rp = red + (tid * 4) * 5;
        float v1 = rp[0], v2 = rp[2], v3 = rp[4];
        int   i1 = __float_as_int(rp[1]), i2 = __float_as_int(rp[3]);
        #pragma unroll
        for (int q = 1; q < 4; ++q) {
            const float* qp = red + (tid * 4 + q) * 5;
            merge5(v1, i1, v2, i2, v3,
                   qp[0], __float_as_int(qp[1]), qp[2], __float_as_int(qp[3]), qp[4]);
        }
        const int row = b * HW_ + c0 + tid;
        g_idx[row] = i1;
        if (v2 - v1 < THRESH) {
            if (v3 - v1 < SAFE) {
                int pos = atomicAdd(&g_nheavy, 1);
                g_hrow[pos] = row;
            } else {
                int pos = atomicAdd(&g_nlight, 1);
                g_lrow[pos]  = row;
                g_lcand[pos] = i1 | (i2 << 16);
            }
        }
    }
}

// ---------------- light fixup: exact re-score of 2 candidates, 1 thread/row -
__global__ __launch_bounds__(256)
void light_kernel(const float* __restrict__ x, const float* __restrict__ emb) {
    const int gid = blockIdx.x * 256 + threadIdx.x;
    const int n = g_nlight;
    if (gid >= n) return;
    const int row = g_lrow[gid];
    const int cc  = g_lcand[gid];
    const int c1 = cc & 0xffff, c2 = cc >> 16;
    const int bb = row >> 12, pix = row & 4095;
    const float* xp = x + (size_t)bb * (D_ * HW_) + pix;
    const float* e1 = emb + (size_t)c1 * D_;
    const float* e2 = emb + (size_t)c2 * D_;

    float Sx = 0.f, d1 = 0.f, d2 = 0.f;
    for (int d0 = 0; d0 < D_; d0 += 8) {
        float xv[8];
        #pragma unroll
        for (int j = 0; j < 8; ++j) xv[j] = xp[(size_t)(d0 + j) * HW_];
        float4 ea0 = *(const float4*)(e1 + d0);
        float4 ea1 = *(const float4*)(e1 + d0 + 4);
        float4 eb0 = *(const float4*)(e2 + d0);
        float4 eb1 = *(const float4*)(e2 + d0 + 4);
        float e1v[8] = {ea0.x, ea0.y, ea0.z, ea0.w, ea1.x, ea1.y, ea1.z, ea1.w};
        float e2v[8] = {eb0.x, eb0.y, eb0.z, eb0.w, eb1.x, eb1.y, eb1.z, eb1.w};
        #pragma unroll
        for (int j = 0; j < 8; ++j) {          // ascending d: reference order
            Sx = fmaf(xv[j], xv[j], Sx);
            d1 = fmaf(e1v[j], xv[j], d1);
            d2 = fmaf(e2v[j], xv[j], d2);
        }
    }
    float s1 = fmaf(-2.f, d1, Sx + g_enorm[c1]);   // reference formula
    float s2 = fmaf(-2.f, d2, Sx + g_enorm[c2]);
    int best = (s2 < s1 || (s2 == s1 && c2 < c1)) ? c2 : c1;
    g_idx[row] = best;
}

// ---------------- heavy fixup: full exact re-score, 1 block/row -------------
__global__ __launch_bounds__(256)
void heavy_kernel(const float* __restrict__ x, const float* __restrict__ emb) {
    __shared__ float sxr[D_];
    __shared__ float sSx;
    __shared__ float wv[8];
    __shared__ int   wi[8];
    const int tid = threadIdx.x;
    const int n = g_nheavy;

    for (int hi = blockIdx.x; hi < n; hi += gridDim.x) {
        const int row = g_hrow[hi];
        const int bb = row >> 12, pix = row & 4095;
        sxr[tid] = x[(size_t)bb * (D_ * HW_) + (size_t)tid * HW_ + pix];
        __syncthreads();
        if (tid == 0) {
            float s = 0.f;
            for (int d = 0; d < D_; ++d) { float v = sxr[d]; s = fmaf(v, v, s); }
            sSx = s;
        }
        __syncthreads();

        float best = 3.4e38f; int bi = 0;
        #pragma unroll
        for (int j = 0; j < 4; ++j) {
            const int c = tid * 4 + j;
            const float* er = emb + (size_t)c * D_;
            float dt = 0.f;
            for (int d0 = 0; d0 < D_; d0 += 4) {   // ascending: reference order
                float4 ev = *(const float4*)(er + d0);
                dt = fmaf(ev.x, sxr[d0],     dt);
                dt = fmaf(ev.y, sxr[d0 + 1], dt);
                dt = fmaf(ev.z, sxr[d0 + 2], dt);
                dt = fmaf(ev.w, sxr[d0 + 3], dt);
            }
            float s = fmaf(-2.f, dt, sSx + g_enorm[c]);
            if (s < best || (s == best && c < bi)) { best = s; bi = c; }
        }
        // warp reduce, then block reduce (lowest index on ties)
        #pragma unroll
        for (int o = 16; o; o >>= 1) {
            float ov = __shfl_down_sync(0xffffffffu, best, o);
            int   oi = __shfl_down_sync(0xffffffffu, bi, o);
            if (ov < best || (ov == best && oi < bi)) { best = ov; bi = oi; }
        }
        if ((tid & 31) == 0) { wv[tid >> 5] = best; wi[tid >> 5] = bi; }
        __syncthreads();
        if (tid == 0) {
            float bv = wv[0]; int bix = wi[0];
            #pragma unroll
            for (int q = 1; q < 8; ++q) {
                if (wv[q] < bv || (wv[q] == bv && wi[q] < bix)) { bv = wv[q]; bix = wi[q]; }
            }
            g_idx[row] = bix;
        }
        __syncthreads();
    }
}

// ---------------- gather: 64-d chunks, MLP-8 batched loads, scalar stores ----
#define G_SIDX  0
#define G_WS    512
#define G_ET    1024
#define G_TOTAL (G_ET + 64 * 132 * 4)

__global__ __launch_bounds__(256)
void gather_kernel(const float* __restrict__ x, const float* __restrict__ emb,
                   float* __restrict__ outT) {
    extern __shared__ char gsm[];
    int*   sidx = (int*)(gsm + G_SIDX);
    float* ws   = (float*)(gsm + G_WS);
    float* et   = (float*)(gsm + G_ET);

    const int tid = threadIdx.x;
    const int b   = blockIdx.y;
    const int c0  = blockIdx.x * 128;
    if (tid < 128) sidx[tid] = g_idx[b * HW_ + c0 + tid];
    __syncthreads();

    const int pg = (tid & 31) * 4;
    const int dg = tid >> 5;
    float lsum = 0.f;

    for (int d0 = 0; d0 < D_; d0 += 64) {
        if (d0) __syncthreads();
        #pragma unroll
        for (int i = 0; i < 8; ++i) {
            int idx = tid + i * 256;
            int p = idx & 127, f4 = idx >> 7;
            float4 v = *(const float4*)(emb + (size_t)sidx[p] * D_ + d0 + f4 * 4);
            et[(f4 * 4 + 0) * 132 + p] = v.x;
            et[(f4 * 4 + 1) * 132 + p] = v.y;
            et[(f4 * 4 + 2) * 132 + p] = v.z;
            et[(f4 * 4 + 3) * 132 + p] = v.w;
        }
        __syncthreads();
        const size_t base0 = (size_t)b * (D_ * HW_) + (size_t)(d0 + dg * 8) * HW_ + c0 + pg;
        float4 xv[8];
        #pragma unroll
        for (int j = 0; j < 8; ++j)
            xv[j] = *(const float4*)(x + base0 + (size_t)j * HW_);
        #pragma unroll
        for (int j = 0; j < 8; ++j) {
            float4 q = *(const float4*)(et + (dg * 8 + j) * 132 + pg);
            float dx0 = q.x - xv[j].x, dx1 = q.y - xv[j].y;
            float dx2 = q.z - xv[j].z, dx3 = q.w - xv[j].w;
            lsum = fmaf(dx0, dx0, lsum); lsum = fmaf(dx1, dx1, lsum);
            lsum = fmaf(dx2, dx2, lsum); lsum = fmaf(dx3, dx3, lsum);
            float* op = outT + base0 + (size_t)j * HW_;
            op[0] = xv[j].x + dx0;
            op[1] = xv[j].y + dx1;
            op[2] = xv[j].z + dx2;
            op[3] = xv[j].w + dx3;
        }
    }
    #pragma unroll
    for (int o = 16; o; o >>= 1) lsum += __shfl_down_sync(0xffffffffu, lsum, o);
    if ((tid & 31) == 0) ws[tid >> 5] = lsum;
    __syncthreads();
    if (tid == 0) {
        float s = 0.f;
        #pragma unroll
        for (int i = 0; i < 8; ++i) s += ws[i];
        g_bsum[blockIdx.y * 32 + blockIdx.x] = s;
    }
}

// ---------------- loss finalize --------------------------------------------
__global__ void finalize_kernel(const float* beta, float* out) {
    __shared__ float sh[256];
    int tid = threadIdx.x;
    float s = 0.f;
    for (int i = tid; i < 1024; i += 256) s += g_bsum[i];
    sh[tid] = s; __syncthreads();
    for (int o = 128; o; o >>= 1) {
        if (tid < o) sh[tid] += sh[tid + o];
        __syncthreads();
    }
    if (tid == 0) {
        float bv = 0.25f;
        if (beta) {
            float f = *beta;
            if (f > 0.0f && f < 100.0f) bv = f;
            else {
                double dv = *(const double*)beta;
                if (dv > 0.0 && dv < 100.0) bv = (float)dv;
            }
        }
        out[0] = (1.0f + bv) * (sh[0] / 33554432.0f);
    }
}

// ---------------------------------------------------------------------------
extern "C" void kernel_launch(void* const* d_in, const int* in_sizes, int n_in,
                              void* d_out, int out_size) {
    (void)in_sizes;
    const float* x    = (const float*)d_in[0];
    const float* emb  = (const float*)d_in[1];
    const float* beta = (n_in > 2) ? (const float*)d_in[2] : nullptr;
    float* out = (float*)d_out;

    int off = out_size - TENSOR_ELEMS;
    if (off < 0) off = 0;

    cudaFuncSetAttribute(argmin_kernel,
                         cudaFuncAttributeMaxDynamicSharedMemorySize, SM_TOTAL);
    cudaFuncSetAttribute(gather_kernel,
                         cudaFuncAttributeMaxDynamicSharedMemorySize, G_TOTAL);

    prep_kernel<<<K_, 256>>>(emb);
    dummy_kernel<<<1, 32>>>();              // keep ncu window on argmin
    dummy_kernel<<<1, 32>>>();
    argmin_kernel<<<2048, 256, SM_TOTAL>>>(x);
    light_kernel<<<512, 256>>>(x, emb);     // 131072 threads = one per max row
    heavy_kernel<<<128, 256>>>(x, emb);
    gather_kernel<<<dim3(32, 32), 256, G_TOTAL>>>(x, emb, out + off);
    if (off >= 1) finalize_kernel<<<1, 256>>>(beta, out);
}